// round 1
// baseline (speedup 1.0000x reference)
#include <cuda_runtime.h>

#define HH 96
#define WW 128
#define CC 21
#define NN (HH*WW)
#define RR 14
#define TAPS (2*RR+1)
#define ITERS 5

// persistent scratch (no allocations allowed)
__device__ float g_u[CC*NN];
__device__ float g_q[CC*NN];
__device__ float g_t[CC*NN];   // after softmax + x-blur
__device__ float g_s[CC*NN];   // after y-blur, normalized
__device__ float g_A[CC*CC];   // compat @ (Ws+Wb)
__device__ float g_w[TAPS];
__device__ float g_nxinv[WW];
__device__ float g_nyinv[HH];

// ---- init: transpose unaries NHWC -> [C, N]; q = u ----
__global__ void k_init_u(const float* __restrict__ un) {
    int idx = blockIdx.x * blockDim.x + threadIdx.x;   // over C*N, ordered (i, c)
    if (idx < CC*NN) {
        int i = idx / CC;
        int c = idx % CC;
        float v = un[idx];          // un[i*C + c], coalesced read
        g_u[c*NN + i] = v;
        g_q[c*NN + i] = v;
    }
}

// ---- init: taps, 1D normalizers, fused 21x21 matrix A ----
__global__ void k_init_small(const float* __restrict__ ws,
                             const float* __restrict__ wb,
                             const float* __restrict__ comp) {
    int t = threadIdx.x;
    if (t < TAPS) {
        float d = (float)(t - RR);
        g_w[t] = expf(-d*d / 18.0f);
    }
    if (t < WW) {
        float s = 0.f;
        for (int d = -RR; d <= RR; d++) {
            int x = t + d;
            if (x >= 0 && x < WW) s += expf(-(float)(d*d) / 18.0f);
        }
        g_nxinv[t] = 1.0f / s;
    }
    if (t < HH) {
        float s = 0.f;
        for (int d = -RR; d <= RR; d++) {
            int y = t + d;
            if (y >= 0 && y < HH) s += expf(-(float)(d*d) / 18.0f);
        }
        g_nyinv[t] = 1.0f / s;
    }
    if (t < CC*CC) {
        int c2 = t / CC, c = t % CC;
        float a = 0.f;
        for (int k = 0; k < CC; k++)
            a += comp[c2*CC + k] * (ws[k*CC + c] + wb[k*CC + c]);
        g_A[t] = a;
    }
}

// ---- per-iteration: softmax over classes + horizontal blur, one block per row ----
__global__ void k_softmax_blurx() {
    __shared__ float sp[CC][WW];
    __shared__ float sw[TAPS];
    int y = blockIdx.x;
    int x = threadIdx.x;         // 0..127
    if (x < TAPS) sw[x] = g_w[x];
    int base = y*WW + x;

    float v[CC];
    float m = -1e30f;
    #pragma unroll
    for (int c = 0; c < CC; c++) {
        v[c] = g_q[c*NN + base];
        m = fmaxf(m, v[c]);
    }
    float s = 0.f;
    #pragma unroll
    for (int c = 0; c < CC; c++) {
        v[c] = __expf(v[c] - m);
        s += v[c];
    }
    float inv = __frcp_rn(s);
    #pragma unroll
    for (int c = 0; c < CC; c++) sp[c][x] = v[c] * inv;
    __syncthreads();

    #pragma unroll
    for (int c = 0; c < CC; c++) {
        float acc = 0.f;
        #pragma unroll
        for (int d = -RR; d <= RR; d++) {
            int xx = x + d;
            if (xx >= 0 && xx < WW) acc += sw[d+RR] * sp[c][xx];
        }
        g_t[c*NN + base] = acc;
    }
}

// ---- per-iteration: vertical blur + normalization, block per (channel, 32-col strip) ----
__global__ void k_blury() {
    __shared__ float tile[HH][32];
    __shared__ float sw[TAPS];
    __shared__ float snyi[HH];
    int c  = blockIdx.x;            // 0..20
    int xb = blockIdx.y;            // 0..3
    int tx = threadIdx.x;           // 0..31
    int ty = threadIdx.y;           // 0..31
    int x  = xb*32 + tx;
    int t  = ty*32 + tx;
    if (t < TAPS) sw[t] = g_w[t];
    if (t < HH)   snyi[t] = g_nyinv[t];
    float nxi = g_nxinv[x];

    for (int yy = ty; yy < HH; yy += 32)
        tile[yy][tx] = g_t[c*NN + yy*WW + x];
    __syncthreads();

    for (int yo = ty; yo < HH; yo += 32) {
        float acc = 0.f;
        #pragma unroll
        for (int d = -RR; d <= RR; d++) {
            int yi = yo + d;
            if (yi >= 0 && yi < HH) acc += sw[d+RR] * tile[yi][tx];
        }
        g_s[c*NN + yo*WW + x] = acc * nxi * snyi[yo];
    }
}

// ---- per-iteration: q = u - A @ s ; last iter writes (1,W,H,C) output ----
__global__ void k_update(float* __restrict__ out, int last) {
    __shared__ float sA[CC*CC];
    int t = threadIdx.x;
    for (int k = t; k < CC*CC; k += blockDim.x) sA[k] = g_A[k];
    __syncthreads();

    int i = blockIdx.x * blockDim.x + t;   // pixel index, grid = exactly N threads
    float sb[CC];
    #pragma unroll
    for (int c = 0; c < CC; c++) sb[c] = g_s[c*NN + i];

    if (!last) {
        #pragma unroll
        for (int c2 = 0; c2 < CC; c2++) {
            float m = 0.f;
            #pragma unroll
            for (int c = 0; c < CC; c++) m += sA[c2*CC + c] * sb[c];
            g_q[c2*NN + i] = g_u[c2*NN + i] - m;
        }
    } else {
        int y = i / WW, x = i % WW;
        int ob = (x*HH + y) * CC;          // out[0, x, y, c]
        #pragma unroll
        for (int c2 = 0; c2 < CC; c2++) {
            float m = 0.f;
            #pragma unroll
            for (int c = 0; c < CC; c++) m += sA[c2*CC + c] * sb[c];
            out[ob + c2] = g_u[c2*NN + i] - m;
        }
    }
}

extern "C" void kernel_launch(void* const* d_in, const int* in_sizes, int n_in,
                              void* d_out, int out_size) {
    const float* un   = (const float*)d_in[0];
    // d_in[1] (rgb) is dead: reference uses spatial_out for both message terms
    const float* ws   = (const float*)d_in[2];
    const float* wb   = (const float*)d_in[3];
    const float* comp = (const float*)d_in[4];
    float* out = (float*)d_out;

    k_init_u<<<(CC*NN + 511)/512, 512>>>(un);
    k_init_small<<<1, 512>>>(ws, wb, comp);
    for (int it = 0; it < ITERS; it++) {
        k_softmax_blurx<<<HH, WW>>>();
        k_blury<<<dim3(CC, 4), dim3(32, 32)>>>();
        k_update<<<NN/128, 128>>>(out, it == ITERS-1);
    }
}

// round 2
// speedup vs baseline: 2.1947x; 2.1947x over previous
#include <cuda_runtime.h>

#define HH 96
#define WW 128
#define CC 21
#define NN (HH*WW)
#define RR 14
#define ITERS 5
#define NBLK HH          // 96 blocks, one per row; <= 148 SMs -> co-resident
#define NTHR 256
#define PH (HH + 2*RR)   // padded rows for g_t: 124

// double-buffered blur-x output, zero-padded by RR rows top/bottom per channel
__device__ float g_t[2][CC][PH*WW];
__device__ unsigned g_barcnt[ITERS];

// cumulative-ticket grid barrier: each launch adds exactly NBLK arrivals per
// counter, so target = next multiple of NBLK above own ticket. Replay-safe,
// wrap-safe (signed compare), no resets needed.
__device__ __forceinline__ void gridbar(int k) {
    __syncthreads();
    __threadfence();
    if (threadIdx.x == 0) {
        unsigned t = atomicAdd(&g_barcnt[k], 1u);
        unsigned target = t - (t % (unsigned)NBLK) + (unsigned)NBLK;
        volatile unsigned* pc = &g_barcnt[k];
        while ((int)(*pc - target) < 0) { }
        __threadfence();
    }
    __syncthreads();
}

__global__ void __launch_bounds__(NTHR, 1) crf_persistent(
    const float* __restrict__ un, const float* __restrict__ ws,
    const float* __restrict__ wb, const float* __restrict__ comp,
    float* __restrict__ out)
{
    // exp(-d*d/18) taps as literals -> FFMA immediates
    const float w[15] = {
        1.0f, 0.9459594f, 0.8007374f, 0.6065307f, 0.4111123f,
        0.2493522f, 0.1353353f, 0.0657285f, 0.0285655f, 0.0111090f,
        0.0038659f, 0.0012039f, 0.00033546f, 0.00008365f, 0.00001866f };

    __shared__ float sp[CC][WW + 2*RR];     // softmax probs, zero-padded in x
    __shared__ float ssum[2][WW];           // softmax partial sums
    __shared__ float msm[2][CC][WW];        // message partials (per group)
    __shared__ __align__(16) float sAt[CC*24];  // A^T = (compat@(Ws+Wb))^T, rows padded to 24

    const int tid = threadIdx.x;
    const int x   = tid & (WW-1);
    const int g   = tid >> 7;               // channel group 0/1
    const int y   = blockIdx.x;
    const int c0  = g * 11;                 // g0: c 0..10, g1: c 11..20

    // ---- one-time init ----
    // A^T[c][c2] = sum_k comp[c2][k]*(ws[k][c]+wb[k][c])
    for (int idx = tid; idx < CC*CC; idx += NTHR) {
        int c2 = idx / CC, c = idx - c2*CC;
        float a = 0.f;
        #pragma unroll
        for (int k = 0; k < CC; k++)
            a += comp[c2*CC+k] * (ws[k*CC+c] + wb[k*CC+c]);
        sAt[c*24 + c2] = a;
    }
    // zero sp x-padding
    for (int idx = tid; idx < CC*2*RR; idx += NTHR) {
        int c = idx / (2*RR), r = idx % (2*RR);
        sp[c][r < RR ? r : r + WW] = 0.f;
    }
    // zero g_t y-padding (distributed across the whole grid)
    for (int idx = blockIdx.x*NTHR + tid; idx < 2*CC*2*RR*WW; idx += NBLK*NTHR) {
        int e = idx;
        int xx = e & (WW-1); e >>= 7;
        int r  = e % (2*RR); e /= (2*RR);
        int c  = e % CC;
        int b  = e / CC;
        int pr = (r < RR) ? r : r + HH;     // rows [0,14) and [110,124)
        g_t[b][c][pr*WW + xx] = 0.f;
    }
    // per-thread normalizers (truncated row sums, matches blur truncation)
    float nx = 0.f, ny = 0.f;
    #pragma unroll
    for (int d = -RR; d <= RR; d++) {
        int ad = d < 0 ? -d : d;
        if ((unsigned)(x+d) < WW) nx += w[ad];
        if ((unsigned)(y+d) < HH) ny += w[ad];
    }
    const float nxinv = 1.0f/nx, nyinv = 1.0f/ny;

    // unaries for own channels -> registers (q never touches memory)
    float u[11], q[11];
    #pragma unroll
    for (int i = 0; i < 11; i++) {
        int c = c0 + i;
        float v = (c < CC) ? un[(y*WW + x)*CC + c] : 0.f;
        u[i] = v; q[i] = v;
    }
    __syncthreads();

    // ---- CRF iterations ----
    for (int it = 0; it < ITERS; it++) {
        float* tb = &g_t[it & 1][0][0];

        // softmax over classes (no max-sub: |q| stays far below exp overflow)
        float p[11]; float ps = 0.f;
        #pragma unroll
        for (int i = 0; i < 11; i++) {
            if (c0 + i < CC) { p[i] = __expf(q[i]); ps += p[i]; }
        }
        ssum[g][x] = ps;
        __syncthreads();
        const float inv = __frcp_rn(ssum[0][x] + ssum[1][x]);
        #pragma unroll
        for (int i = 0; i < 11; i++)
            if (c0 + i < CC) sp[c0+i][x + RR] = p[i] * inv;
        __syncthreads();

        // blur-x (smem, padded -> no guards), fold in 1/nx, write padded g_t
        #pragma unroll
        for (int i = 0; i < 11; i++) {
            int c = c0 + i;
            if (c < CC) {
                float acc = 0.f;
                #pragma unroll
                for (int d = -RR; d <= RR; d++)
                    acc += w[d < 0 ? -d : d] * sp[c][x + RR + d];
                tb[c*(PH*WW) + (y + RR)*WW + x] = acc * nxinv;
            }
        }

        gridbar(it);   // all rows' blur-x visible in L2

        // blur-y (cross-block -> __ldcg) + fused 21x21 message matvec
        float pm[CC];
        #pragma unroll
        for (int c2 = 0; c2 < CC; c2++) pm[c2] = 0.f;
        #pragma unroll
        for (int i = 0; i < 11; i++) {
            int c = c0 + i;
            if (c < CC) {
                const float* col = &tb[c*(PH*WW) + y*WW + x]; // padded: rows y..y+28
                float acc = 0.f;
                #pragma unroll
                for (int d = -RR; d <= RR; d++)
                    acc += w[d < 0 ? -d : d] * __ldcg(&col[(d + RR)*WW]);
                const float s = acc * nyinv;
                const float4* ar = (const float4*)&sAt[c*24];
                float4 a0 = ar[0], a1 = ar[1], a2 = ar[2], a3 = ar[3], a4 = ar[4];
                float  a20 = sAt[c*24 + 20];
                pm[0]  += a0.x*s; pm[1]  += a0.y*s; pm[2]  += a0.z*s; pm[3]  += a0.w*s;
                pm[4]  += a1.x*s; pm[5]  += a1.y*s; pm[6]  += a1.z*s; pm[7]  += a1.w*s;
                pm[8]  += a2.x*s; pm[9]  += a2.y*s; pm[10] += a2.z*s; pm[11] += a2.w*s;
                pm[12] += a3.x*s; pm[13] += a3.y*s; pm[14] += a3.z*s; pm[15] += a3.w*s;
                pm[16] += a4.x*s; pm[17] += a4.y*s; pm[18] += a4.z*s; pm[19] += a4.w*s;
                pm[20] += a20*s;
            }
        }
        // combine the two groups' partial messages; update q (or write output)
        #pragma unroll
        for (int c2 = 0; c2 < CC; c2++) msm[g][c2][x] = pm[c2];
        __syncthreads();
        if (it < ITERS-1) {
            if (g == 0) {
                #pragma unroll
                for (int i = 0; i < 11; i++)
                    q[i] = u[i] - (pm[i] + msm[1][i][x]);
            } else {
                #pragma unroll
                for (int i = 0; i < 10; i++)
                    q[i] = u[i] - (pm[11+i] + msm[0][11+i][x]);
            }
        } else {
            const int ob = (x*HH + y)*CC;   // out[0, x, y, c]
            if (g == 0) {
                #pragma unroll
                for (int i = 0; i < 11; i++)
                    out[ob + i] = u[i] - (pm[i] + msm[1][i][x]);
            } else {
                #pragma unroll
                for (int i = 0; i < 10; i++)
                    out[ob + 11 + i] = u[i] - (pm[11+i] + msm[0][11+i][x]);
            }
        }
    }
}

extern "C" void kernel_launch(void* const* d_in, const int* in_sizes, int n_in,
                              void* d_out, int out_size) {
    const float* un   = (const float*)d_in[0];
    // d_in[1] (rgb) is dead: reference uses spatial_out for both message terms
    const float* ws   = (const float*)d_in[2];
    const float* wb   = (const float*)d_in[3];
    const float* comp = (const float*)d_in[4];
    crf_persistent<<<NBLK, NTHR>>>(un, ws, wb, comp, (float*)d_out);
}

// round 3
// speedup vs baseline: 2.6811x; 1.2216x over previous
#include <cuda_runtime.h>

#define HH 96
#define WW 128
#define CC 21
#define NN (HH*WW)
#define RR 14
#define ITERS 5
#define NBLK HH          // 96 blocks, one per row; <= 148 SMs -> co-resident
#define NTHR 512
#define NGRP 4
#define PH (HH + 2*RR)   // padded rows for g_t: 124

// double-buffered blur-x output, zero-padded by RR rows top/bottom per channel
__device__ float g_t[2][CC][PH*WW];
__device__ unsigned g_barcnt[ITERS];

// cumulative-ticket grid barrier: replay-safe (each replay adds exactly NBLK
// arrivals per counter), wrap-safe (signed compare).
__device__ __forceinline__ void gridbar(int k) {
    __syncthreads();
    __threadfence();
    if (threadIdx.x == 0) {
        unsigned t = atomicAdd(&g_barcnt[k], 1u);
        unsigned target = t - (t % (unsigned)NBLK) + (unsigned)NBLK;
        volatile unsigned* pc = &g_barcnt[k];
        while ((int)(*pc - target) < 0) { }
        __threadfence();
    }
    __syncthreads();
}

__global__ void __launch_bounds__(NTHR, 1) crf_persistent(
    const float* __restrict__ un, const float* __restrict__ ws,
    const float* __restrict__ wb, const float* __restrict__ comp,
    float* __restrict__ out)
{
    // exp(-d*d/18) taps as literals -> FFMA immediates
    const float w[15] = {
        1.0f, 0.9459594f, 0.8007374f, 0.6065307f, 0.4111123f,
        0.2493522f, 0.1353353f, 0.0657285f, 0.0285655f, 0.0111090f,
        0.0038659f, 0.0012039f, 0.00033546f, 0.00008365f, 0.00001866f };

    __shared__ float sp[CC][WW + 2*RR];       // softmax probs, zero-padded in x
    __shared__ float ssum[NGRP][WW];          // softmax partial sums
    __shared__ float msm[2][CC][WW];          // 2-stage message reduction buffers
    __shared__ __align__(16) float sAt[CC*24];// A^T rows padded to 24

    const int tid = threadIdx.x;
    const int x   = tid & (WW-1);
    const int g   = tid >> 7;                 // channel group 0..3; owns c = g + 4*i
    const int y   = blockIdx.x;

    // ---- one-time init ----
    // A^T[c][c2] = sum_k comp[c2][k]*(ws[k][c]+wb[k][c])
    for (int idx = tid; idx < CC*CC; idx += NTHR) {
        int c2 = idx / CC, c = idx - c2*CC;
        float a = 0.f;
        #pragma unroll
        for (int k = 0; k < CC; k++)
            a += comp[c2*CC+k] * (ws[k*CC+c] + wb[k*CC+c]);
        sAt[c*24 + c2] = a;
    }
    // zero sp x-padding
    for (int idx = tid; idx < CC*2*RR; idx += NTHR) {
        int c = idx / (2*RR), r = idx % (2*RR);
        sp[c][r < RR ? r : r + WW] = 0.f;
    }
    // zero g_t y-padding (distributed across the whole grid)
    for (int idx = blockIdx.x*NTHR + tid; idx < 2*CC*2*RR*WW; idx += NBLK*NTHR) {
        int e = idx;
        int xx = e & (WW-1); e >>= 7;
        int r  = e % (2*RR); e /= (2*RR);
        int c  = e % CC;
        int b  = e / CC;
        int pr = (r < RR) ? r : r + HH;       // rows [0,14) and [110,124)
        g_t[b][c][pr*WW + xx] = 0.f;
    }
    // per-thread normalizers (truncated row sums matching blur truncation)
    float nx = 0.f, ny = 0.f;
    #pragma unroll
    for (int d = -RR; d <= RR; d++) {
        int ad = d < 0 ? -d : d;
        if ((unsigned)(x+d) < WW) nx += w[ad];
        if ((unsigned)(y+d) < HH) ny += w[ad];
    }
    const float nxinv = 1.0f/nx, nyinv = 1.0f/ny;

    // unaries for own (strided) channels -> registers
    float u[6], q[6];
    #pragma unroll
    for (int i = 0; i < 6; i++) {
        int c = g + 4*i;
        float v = (c < CC) ? un[(y*WW + x)*CC + c] : 0.f;
        u[i] = v; q[i] = v;
    }
    __syncthreads();

    // ---- CRF iterations ----
    for (int it = 0; it < ITERS; it++) {
        float* tb = &g_t[it & 1][0][0];

        // softmax over classes (no max-sub: q stays far below exp overflow)
        float p[6]; float ps = 0.f;
        #pragma unroll
        for (int i = 0; i < 6; i++) {
            int c = g + 4*i;
            if (c < CC) { p[i] = __expf(q[i]); ps += p[i]; }
        }
        ssum[g][x] = ps;
        __syncthreads();
        const float inv = __frcp_rn(ssum[0][x] + ssum[1][x] + ssum[2][x] + ssum[3][x]);
        #pragma unroll
        for (int i = 0; i < 6; i++) {
            int c = g + 4*i;
            if (c < CC) sp[c][x + RR] = p[i] * inv;
        }
        __syncthreads();

        // blur-x (smem, padded -> no guards), fold in 1/nx, write padded g_t
        #pragma unroll
        for (int i = 0; i < 6; i++) {
            int c = g + 4*i;
            if (c < CC) {
                float acc = 0.f;
                #pragma unroll
                for (int d = -RR; d <= RR; d++)
                    acc += w[d < 0 ? -d : d] * sp[c][x + RR + d];
                tb[c*(PH*WW) + (y + RR)*WW + x] = acc * nxinv;
            }
        }

        gridbar(it);   // all rows' blur-x visible in L2

        // blur-y (cross-block -> __ldcg) + fused 21x21 message matvec (partial)
        float pm[CC];
        #pragma unroll
        for (int c2 = 0; c2 < CC; c2++) pm[c2] = 0.f;
        #pragma unroll
        for (int i = 0; i < 6; i++) {
            int c = g + 4*i;
            if (c < CC) {
                const float* col = &tb[c*(PH*WW) + y*WW + x]; // padded rows y..y+28
                float acc = 0.f;
                #pragma unroll
                for (int d = -RR; d <= RR; d++)
                    acc += w[d < 0 ? -d : d] * __ldcg(&col[(d + RR)*WW]);
                const float s = acc * nyinv;
                const float4* ar = (const float4*)&sAt[c*24];
                float4 a0 = ar[0], a1 = ar[1], a2 = ar[2], a3 = ar[3], a4 = ar[4];
                float  a20 = sAt[c*24 + 20];
                pm[0]  += a0.x*s; pm[1]  += a0.y*s; pm[2]  += a0.z*s; pm[3]  += a0.w*s;
                pm[4]  += a1.x*s; pm[5]  += a1.y*s; pm[6]  += a1.z*s; pm[7]  += a1.w*s;
                pm[8]  += a2.x*s; pm[9]  += a2.y*s; pm[10] += a2.z*s; pm[11] += a2.w*s;
                pm[12] += a3.x*s; pm[13] += a3.y*s; pm[14] += a3.z*s; pm[15] += a3.w*s;
                pm[16] += a4.x*s; pm[17] += a4.y*s; pm[18] += a4.z*s; pm[19] += a4.w*s;
                pm[20] += a20*s;
            }
        }
        // 2-stage 4-way combine through 2 smem buffers:
        //   stage 1: groups 2,3 publish; groups 0,1 absorb (0<-2, 1<-3)
        //   stage 2: groups 0,1 publish combined halves; everyone sums both
        if (g >= 2) {
            #pragma unroll
            for (int c2 = 0; c2 < CC; c2++) msm[g-2][c2][x] = pm[c2];
        }
        __syncthreads();
        if (g < 2) {
            #pragma unroll
            for (int c2 = 0; c2 < CC; c2++) {
                pm[c2] += msm[g][c2][x];
                msm[g][c2][x] = pm[c2];
            }
        }
        __syncthreads();
        if (it < ITERS-1) {
            #pragma unroll
            for (int i = 0; i < 6; i++) {
                int c = g + 4*i;
                if (c < CC) q[i] = u[i] - (msm[0][c][x] + msm[1][c][x]);
            }
        } else {
            const int ob = (x*HH + y)*CC;   // out[0, x, y, c]
            #pragma unroll
            for (int i = 0; i < 6; i++) {
                int c = g + 4*i;
                if (c < CC) out[ob + c] = u[i] - (msm[0][c][x] + msm[1][c][x]);
            }
        }
    }
}

extern "C" void kernel_launch(void* const* d_in, const int* in_sizes, int n_in,
                              void* d_out, int out_size) {
    const float* un   = (const float*)d_in[0];
    // d_in[1] (rgb) is dead: reference uses spatial_out for both message terms
    const float* ws   = (const float*)d_in[2];
    const float* wb   = (const float*)d_in[3];
    const float* comp = (const float*)d_in[4];
    crf_persistent<<<NBLK, NTHR>>>(un, ws, wb, comp, (float*)d_out);
}